// round 2
// baseline (speedup 1.0000x reference)
#include <cuda_runtime.h>
#include <cuda_bf16.h>
#include <math.h>

// ---------------------------------------------------------------------------
// Problem constants
// ---------------------------------------------------------------------------
#define BGR   16384            // graphs
#define NPG   9                // nodes per graph
#define NNODE (BGR * NPG)      // 147456
#define DMODEL 128
#define DFF    512
#define NLAYER 4
#define EPG    16

// Old-style (broadcast) GEMM tiling for gcn
#define MC       64
#define NC       128
#define NTHREADS 128
#define SA_LD    132
#define SMEM_FLOATS (NC * DMODEL + MC * SA_LD)
#define SMEM_BYTES  (SMEM_FLOATS * 4)            // 99328

// k-split GEMM tiling (ffn1/ffn2): 64x64 tile, 128 threads, 8x4/thread
#define KS_SMEM_BYTES (2 * 64 * 132 * 4)         // 67584

// ---------------------------------------------------------------------------
// Scratch (device globals; no runtime allocation allowed)
// ---------------------------------------------------------------------------
__device__ float g_h  [(size_t)NNODE * DMODEL];   // 75.5 MB activations
__device__ float g_agg[(size_t)NNODE * DMODEL];   // 75.5 MB aggregated
__device__ float g_mid[(size_t)NNODE * DFF];      // 302 MB FFN mid
__device__ float g_inv[NNODE];                    // 1/sqrt(deg)
__device__ float g_W1T[(size_t)NLAYER * DFF * DMODEL];   // W1 transposed [l][n][k]
__device__ float g_W2T[(size_t)NLAYER * DMODEL * DFF];   // W2 transposed [l][n][k]

typedef unsigned long long ull;

// ---------------------------------------------------------------------------
// f32x2 packed-FMA helpers (sm_100+)
// ---------------------------------------------------------------------------
__device__ __forceinline__ ull pk2(float x, float y) {
    ull r;
    asm("mov.b64 %0, {%1, %2};" : "=l"(r) : "f"(x), "f"(y));
    return r;
}
__device__ __forceinline__ void upk2(ull v, float &x, float &y) {
    asm("mov.b64 {%0, %1}, %2;" : "=f"(x), "=f"(y) : "l"(v));
}
__device__ __forceinline__ void fma2(ull &c, ull a, ull b) {
    asm("fma.rn.f32x2 %0, %1, %2, %0;" : "+l"(c) : "l"(a), "l"(b));
}

// ---------------------------------------------------------------------------
// Weight transpose:  dst[c][r] = src[r][c], per-matrix in z
// ---------------------------------------------------------------------------
__global__ void transpose_kernel(const float* __restrict__ src,
                                 float* __restrict__ dst, int R, int C) {
    __shared__ float t[32][33];
    int l = blockIdx.z;
    const float* s = src + (size_t)l * R * C;
    float* d = dst + (size_t)l * R * C;
    int bx = blockIdx.x * 32;   // col tile of src
    int by = blockIdx.y * 32;   // row tile of src
    int tx = threadIdx.x, ty = threadIdx.y;   // 32 x 8
#pragma unroll
    for (int j = 0; j < 32; j += 8)
        t[ty + j][tx] = s[(size_t)(by + ty + j) * C + bx + tx];
    __syncthreads();
#pragma unroll
    for (int j = 0; j < 32; j += 8)
        d[(size_t)(bx + ty + j) * R + by + tx] = t[tx][ty + j];
}

// ---------------------------------------------------------------------------
// Tile loaders
// ---------------------------------------------------------------------------
// 64 rows x 128 cols -> smem stride 132 (conflict-free, float4 aligned)
__device__ __forceinline__ void ldtile64(const float* __restrict__ g, int ldg,
                                         int row0, int col0, float* s, int tid) {
#pragma unroll
    for (int i = 0; i < 16; i++) {
        int f4 = tid + 128 * i;            // 2048 float4s
        int m  = f4 >> 5;
        int c4 = f4 & 31;
        *reinterpret_cast<float4*>(s + m * 132 + c4 * 4) =
            *reinterpret_cast<const float4*>(g + (size_t)(row0 + m) * ldg + col0 + c4 * 4);
    }
}

// old-style loaders for gcn
__device__ __forceinline__ void load_A_tile(const float* __restrict__ A, int lda_g,
                                            int m0, int k0, float* sA, int tid) {
#pragma unroll
    for (int i = 0; i < 16; i++) {
        int f4 = tid + NTHREADS * i;
        int m  = f4 >> 5;
        int c4 = f4 & 31;
        float4 v = *reinterpret_cast<const float4*>(
            A + (size_t)(m0 + m) * lda_g + k0 + c4 * 4);
        *reinterpret_cast<float4*>(sA + m * SA_LD + c4 * 4) = v;
    }
}
__device__ __forceinline__ void load_W_tile(const float* __restrict__ W, int ldw_g,
                                            int k0, int n0, float* sW, int tid) {
#pragma unroll
    for (int i = 0; i < 32; i++) {
        int f4 = tid + NTHREADS * i;
        int k  = f4 >> 5;
        int c4 = f4 & 31;
        float4 v = *reinterpret_cast<const float4*>(
            W + (size_t)(k0 + k) * ldw_g + n0 + c4 * 4);
        *reinterpret_cast<float4*>(sW + k * NC + c4 * 4) = v;
    }
}

// ---------------------------------------------------------------------------
// k-split GEMM core: C(64x64) += A(64x128) @ W^T(64x128)^T
// per-thread 8 rows (tm + 8i, tm = tid&7) x 4 cols (4*tn + j, tn = tid>>3).
// Each acc holds (even-k partial, odd-k partial); both operands are natural
// k-contiguous vectors -> ZERO broadcast movs in the inner loop.
// ---------------------------------------------------------------------------
__device__ __forceinline__ void gemm_ks(const float* __restrict__ sA,
                                        const float* __restrict__ sW,
                                        int tm, int tn, ull acc[8][4]) {
#pragma unroll 4
    for (int kk = 0; kk < DMODEL; kk += 4) {
        ulonglong2 b0 = *reinterpret_cast<const ulonglong2*>(sW + (4 * tn + 0) * 132 + kk);
        ulonglong2 b1 = *reinterpret_cast<const ulonglong2*>(sW + (4 * tn + 1) * 132 + kk);
        ulonglong2 b2 = *reinterpret_cast<const ulonglong2*>(sW + (4 * tn + 2) * 132 + kk);
        ulonglong2 b3 = *reinterpret_cast<const ulonglong2*>(sW + (4 * tn + 3) * 132 + kk);
#pragma unroll
        for (int i = 0; i < 8; i++) {
            ulonglong2 a = *reinterpret_cast<const ulonglong2*>(sA + (tm + 8 * i) * 132 + kk);
            fma2(acc[i][0], a.x, b0.x);  fma2(acc[i][0], a.y, b0.y);
            fma2(acc[i][1], a.x, b1.x);  fma2(acc[i][1], a.y, b1.y);
            fma2(acc[i][2], a.x, b2.x);  fma2(acc[i][2], a.y, b2.y);
            fma2(acc[i][3], a.x, b3.x);  fma2(acc[i][3], a.y, b3.y);
        }
    }
}

__device__ __forceinline__ void ks_init_bias(const float* __restrict__ bias,
                                             int n0, int tn, ull acc[8][4]) {
    float4 bb = *reinterpret_cast<const float4*>(bias + n0 + tn * 4);
    ull i0 = pk2(bb.x, 0.f), i1 = pk2(bb.y, 0.f), i2 = pk2(bb.z, 0.f), i3 = pk2(bb.w, 0.f);
#pragma unroll
    for (int i = 0; i < 8; i++) {
        acc[i][0] = i0; acc[i][1] = i1; acc[i][2] = i2; acc[i][3] = i3;
    }
}

// ---------------------------------------------------------------------------
// old broadcast-style GEMM core (gcn only)
// ---------------------------------------------------------------------------
__device__ __forceinline__ void gemm128(const float* __restrict__ sA,
                                        const float* __restrict__ sW,
                                        int tm, int tn, ull acc[8][4]) {
#pragma unroll 8
    for (int k = 0; k < DMODEL; k++) {
        float4 b0 = *reinterpret_cast<const float4*>(sW + k * NC + tn * 8);
        float4 b1 = *reinterpret_cast<const float4*>(sW + k * NC + tn * 8 + 4);
        ull bv0 = pk2(b0.x, b0.y), bv1 = pk2(b0.z, b0.w);
        ull bv2 = pk2(b1.x, b1.y), bv3 = pk2(b1.z, b1.w);
#pragma unroll
        for (int i = 0; i < 8; i++) {
            float a = sA[(tm + 8 * i) * SA_LD + k];
            ull av = pk2(a, a);
            fma2(acc[i][0], av, bv0);
            fma2(acc[i][1], av, bv1);
            fma2(acc[i][2], av, bv2);
            fma2(acc[i][3], av, bv3);
        }
    }
}

__device__ __forceinline__ void init_acc_bias(const float* __restrict__ bias,
                                              int n_off, int tn, ull acc[8][4]) {
    float4 bb0 = *reinterpret_cast<const float4*>(bias + n_off + tn * 8);
    float4 bb1 = *reinterpret_cast<const float4*>(bias + n_off + tn * 8 + 4);
    ull i0 = pk2(bb0.x, bb0.y), i1 = pk2(bb0.z, bb0.w);
    ull i2 = pk2(bb1.x, bb1.y), i3 = pk2(bb1.z, bb1.w);
#pragma unroll
    for (int i = 0; i < 8; i++) {
        acc[i][0] = i0; acc[i][1] = i1; acc[i][2] = i2; acc[i][3] = i3;
    }
}

// ---------------------------------------------------------------------------
// K0: degree -> inv_sqrt_deg
// ---------------------------------------------------------------------------
__global__ void deg_kernel(const int* __restrict__ dst) {
    int g = blockIdx.x * blockDim.x + threadIdx.x;
    if (g >= BGR) return;
    int base = g * NPG;
    int cnt[NPG];
#pragma unroll
    for (int j = 0; j < NPG; j++) cnt[j] = 1;
#pragma unroll
    for (int e = 0; e < EPG; e++) {
        int dl = dst[g * EPG + e] - base;
#pragma unroll
        for (int j = 0; j < NPG; j++) cnt[j] += (dl == j) ? 1 : 0;
    }
#pragma unroll
    for (int j = 0; j < NPG; j++)
        g_inv[base + j] = rsqrtf((float)cnt[j]);
}

// ---------------------------------------------------------------------------
// K1: embedding
// ---------------------------------------------------------------------------
__global__ void embed_kernel(const float4* __restrict__ opt,
                             const float4* __restrict__ de,
                             const int* __restrict__ op_idx) {
    int idx = blockIdx.x * blockDim.x + threadIdx.x;
    int n = idx >> 5, c = idx & 31;
    int op = op_idx[n];
    float4 t = opt[op * 32 + c];
    float4 d = de[c];
    float4 o = make_float4(t.x + d.x, t.y + d.y, t.z + d.z, t.w + d.w);
    reinterpret_cast<float4*>(g_h)[idx] = o;
}

// ---------------------------------------------------------------------------
// K2: per-graph aggregation (no atomics)
// ---------------------------------------------------------------------------
__global__ __launch_bounds__(128) void agg_kernel(const int* __restrict__ src,
                                                  const int* __restrict__ dst) {
    __shared__ float hs[NPG * DMODEL];
    __shared__ float ag[NPG * DMODEL];
    __shared__ float invs[NPG];
    __shared__ float we[EPG];
    __shared__ int sl[EPG], dl[EPG];

    int g = blockIdx.x, t = threadIdx.x;
    int nbase = g * NPG;
    if (t < NPG) invs[t] = g_inv[nbase + t];
    if (t < EPG) {
        sl[t] = src[g * EPG + t] - nbase;
        dl[t] = dst[g * EPG + t] - nbase;
    }
    __syncthreads();
    if (t < EPG) we[t] = invs[sl[t]] * invs[dl[t]];
#pragma unroll
    for (int j = 0; j < NPG; j++) {
        float v = g_h[(size_t)(nbase + j) * DMODEL + t];
        hs[j * DMODEL + t] = v;
        ag[j * DMODEL + t] = invs[j] * invs[j] * v;
    }
    __syncthreads();
#pragma unroll
    for (int e = 0; e < EPG; e++)
        ag[dl[e] * DMODEL + t] += we[e] * hs[sl[e] * DMODEL + t];
#pragma unroll
    for (int j = 0; j < NPG; j++)
        g_agg[(size_t)(nbase + j) * DMODEL + t] = ag[j * DMODEL + t];
}

// ---------------------------------------------------------------------------
// K3: GCN GEMM + bias + relu + LayerNorm (broadcast-style, NC=128 for LN)
// ---------------------------------------------------------------------------
__global__ __launch_bounds__(NTHREADS) void gcn_kernel(const float* __restrict__ W,
                                                       const float* __restrict__ bias,
                                                       const float* __restrict__ lng,
                                                       const float* __restrict__ lnb) {
    extern __shared__ float smem[];
    float* sW = smem;
    float* sA = smem + NC * DMODEL;
    int tid = threadIdx.x;
    int tm = tid & 7, tn = tid >> 3;
    int m0 = blockIdx.x * MC;

    load_A_tile(g_agg, DMODEL, m0, 0, sA, tid);
    load_W_tile(W, DMODEL, 0, 0, sW, tid);

    ull acc[8][4];
    init_acc_bias(bias, 0, tn, acc);
    __syncthreads();
    gemm128(sA, sW, tm, tn, acc);
    __syncthreads();

    float* sC = sA;
#pragma unroll
    for (int i = 0; i < 8; i++) {
        int r = tm + 8 * i;
        float c0, c1, c2, c3, c4, c5, c6, c7;
        upk2(acc[i][0], c0, c1); upk2(acc[i][1], c2, c3);
        upk2(acc[i][2], c4, c5); upk2(acc[i][3], c6, c7);
        float4 o0 = make_float4(fmaxf(c0, 0.f), fmaxf(c1, 0.f), fmaxf(c2, 0.f), fmaxf(c3, 0.f));
        float4 o1 = make_float4(fmaxf(c4, 0.f), fmaxf(c5, 0.f), fmaxf(c6, 0.f), fmaxf(c7, 0.f));
        *reinterpret_cast<float4*>(sC + r * SA_LD + tn * 8)     = o0;
        *reinterpret_cast<float4*>(sC + r * SA_LD + tn * 8 + 4) = o1;
    }
    __syncthreads();

    int w = tid >> 5, lane = tid & 31;
    float4 gq = *reinterpret_cast<const float4*>(lng + lane * 4);
    float4 bq = *reinterpret_cast<const float4*>(lnb + lane * 4);
    for (int it = 0; it < 16; it++) {
        int r = w * 16 + it;
        float4 x = *reinterpret_cast<const float4*>(sC + r * SA_LD + lane * 4);
        float s = x.x + x.y + x.z + x.w;
#pragma unroll
        for (int o = 16; o; o >>= 1) s += __shfl_xor_sync(0xffffffffu, s, o);
        float mu = s * (1.f / 128.f);
        float dx = x.x - mu, dy = x.y - mu, dz = x.z - mu, dw = x.w - mu;
        float q = dx * dx + dy * dy + dz * dz + dw * dw;
#pragma unroll
        for (int o = 16; o; o >>= 1) q += __shfl_xor_sync(0xffffffffu, q, o);
        float rs = rsqrtf(q * (1.f / 128.f) + 1e-5f);
        float4 o4 = make_float4(dx * rs * gq.x + bq.x, dy * rs * gq.y + bq.y,
                                dz * rs * gq.z + bq.z, dw * rs * gq.w + bq.w);
        *reinterpret_cast<float4*>(g_h + (size_t)(m0 + r) * DMODEL + lane * 4) = o4;
    }
}

// ---------------------------------------------------------------------------
// K4: FFN1 (k-split): one block does 64 rows x ALL 512 ff-cols (A loaded once)
// ---------------------------------------------------------------------------
__global__ __launch_bounds__(128, 3) void ffn1_ks(const float* __restrict__ W1T,
                                                  const float* __restrict__ b1l) {
    extern __shared__ float smem[];
    float* sA = smem;
    float* sW = smem + 64 * 132;
    int tid = threadIdx.x;
    int tm = tid & 7, tn = tid >> 3;
    int m0 = blockIdx.x * 64;

    ldtile64(g_h, DMODEL, m0, 0, sA, tid);

    for (int c = 0; c < 8; c++) {
        int n0 = c * 64;
        ldtile64(W1T, DMODEL, n0, 0, sW, tid);
        ull acc[8][4];
        ks_init_bias(b1l, n0, tn, acc);
        __syncthreads();
        gemm_ks(sA, sW, tm, tn, acc);
#pragma unroll
        for (int i = 0; i < 8; i++) {
            int row = m0 + tm + 8 * i;
            float l0, h0, l1, h1, l2, h2, l3, h3;
            upk2(acc[i][0], l0, h0); upk2(acc[i][1], l1, h1);
            upk2(acc[i][2], l2, h2); upk2(acc[i][3], l3, h3);
            float4 o = make_float4(fmaxf(l0 + h0, 0.f), fmaxf(l1 + h1, 0.f),
                                   fmaxf(l2 + h2, 0.f), fmaxf(l3 + h3, 0.f));
            *reinterpret_cast<float4*>(g_mid + (size_t)row * DFF + n0 + tn * 4) = o;
        }
        __syncthreads();   // done reading sW before next chunk overwrites
    }
}

// ---------------------------------------------------------------------------
// K5: FFN2 (k-split):  g_h = g_h + g_mid @ W2 + b2,  K = 512 in 4 chunks
// ---------------------------------------------------------------------------
__global__ __launch_bounds__(128, 3) void ffn2_ks(const float* __restrict__ W2T,
                                                  const float* __restrict__ b2l) {
    extern __shared__ float smem[];
    float* sA = smem;
    float* sW = smem + 64 * 132;
    int tid = threadIdx.x;
    int tm = tid & 7, tn = tid >> 3;
    int m0 = blockIdx.x * 64;
    int n0 = blockIdx.y * 64;

    ull acc[8][4];
    ks_init_bias(b2l, n0, tn, acc);

    for (int kc = 0; kc < 4; kc++) {
        __syncthreads();
        ldtile64(g_mid, DFF, m0, kc * DMODEL, sA, tid);
        ldtile64(W2T, DFF, n0, kc * DMODEL, sW, tid);
        __syncthreads();
        gemm_ks(sA, sW, tm, tn, acc);
    }

#pragma unroll
    for (int i = 0; i < 8; i++) {
        int row = m0 + tm + 8 * i;
        float l0, h0, l1, h1, l2, h2, l3, h3;
        upk2(acc[i][0], l0, h0); upk2(acc[i][1], l1, h1);
        upk2(acc[i][2], l2, h2); upk2(acc[i][3], l3, h3);
        float* p = g_h + (size_t)row * DMODEL + n0 + tn * 4;
        float4 r = *reinterpret_cast<const float4*>(p);
        float4 o = make_float4(l0 + h0 + r.x, l1 + h1 + r.y,
                               l2 + h2 + r.z, l3 + h3 + r.w);
        *reinterpret_cast<float4*>(p) = o;
    }
}

// ---------------------------------------------------------------------------
// K6: readout
// ---------------------------------------------------------------------------
__global__ __launch_bounds__(128) void readout_kernel(const float4* __restrict__ fcw,
                                                      const float* __restrict__ fcb,
                                                      float* __restrict__ out) {
    int w = threadIdx.x >> 5, lane = threadIdx.x & 31;
    int g = blockIdx.x * 4 + w;
    const float4* h4 = reinterpret_cast<const float4*>(g_h);
    size_t base = (size_t)g * NPG * 32;
    float4 s = make_float4(0.f, 0.f, 0.f, 0.f);
#pragma unroll
    for (int j = 0; j < NPG; j++) {
        float4 v = h4[base + j * 32 + lane];
        s.x += v.x; s.y += v.y; s.z += v.z; s.w += v.w;
    }
    float4 wv = fcw[lane];
    float p = s.x * wv.x + s.y * wv.y + s.z * wv.z + s.w * wv.w;
#pragma unroll
    for (int o = 16; o; o >>= 1) p += __shfl_xor_sync(0xffffffffu, p, o);
    if (lane == 0)
        out[g] = 1.f / (1.f + expf(-(p * (1.f / 9.f) + fcb[0])));
}

// ---------------------------------------------------------------------------
// Launcher
// ---------------------------------------------------------------------------
extern "C" void kernel_launch(void* const* d_in, const int* in_sizes, int n_in,
                              void* d_out, int out_size) {
    const float* op_table   = (const float*)d_in[0];
    const float* device_emb = (const float*)d_in[1];
    const float* Wg         = (const float*)d_in[2];
    const float* bg         = (const float*)d_in[3];
    const float* ln_g       = (const float*)d_in[4];
    const float* ln_b       = (const float*)d_in[5];
    const float* W1         = (const float*)d_in[6];
    const float* b1         = (const float*)d_in[7];
    const float* W2         = (const float*)d_in[8];
    const float* b2         = (const float*)d_in[9];
    const float* fc_w       = (const float*)d_in[10];
    const float* fc_b       = (const float*)d_in[11];
    const int*   op_idx     = (const int*)d_in[12];
    const int*   src        = (const int*)d_in[13];
    const int*   dst        = (const int*)d_in[14];
    float* out = (float*)d_out;

    cudaFuncSetAttribute(gcn_kernel, cudaFuncAttributeMaxDynamicSharedMemorySize, SMEM_BYTES);
    cudaFuncSetAttribute(ffn1_ks,    cudaFuncAttributeMaxDynamicSharedMemorySize, KS_SMEM_BYTES);
    cudaFuncSetAttribute(ffn2_ks,    cudaFuncAttributeMaxDynamicSharedMemorySize, KS_SMEM_BYTES);

    float* w1t; cudaGetSymbolAddress((void**)&w1t, g_W1T);
    float* w2t; cudaGetSymbolAddress((void**)&w2t, g_W2T);

    // transpose W1 [l][128][512] -> W1T [l][512][128]; W2 [l][512][128] -> [l][128][512]
    transpose_kernel<<<dim3(DFF / 32, DMODEL / 32, NLAYER), dim3(32, 8)>>>(W1, w1t, DMODEL, DFF);
    transpose_kernel<<<dim3(DMODEL / 32, DFF / 32, NLAYER), dim3(32, 8)>>>(W2, w2t, DFF, DMODEL);

    deg_kernel<<<BGR / 256, 256>>>(dst);
    embed_kernel<<<(NNODE * 32) / 256, 256>>>(
        (const float4*)op_table, (const float4*)device_emb, op_idx);

    for (int l = 0; l < NLAYER; l++) {
        agg_kernel<<<BGR, 128>>>(src, dst);
        gcn_kernel<<<NNODE / MC, NTHREADS, SMEM_BYTES>>>(
            Wg + (size_t)l * DMODEL * DMODEL, bg + l * DMODEL,
            ln_g + l * DMODEL, ln_b + l * DMODEL);
        ffn1_ks<<<NNODE / 64, 128, KS_SMEM_BYTES>>>(
            w1t + (size_t)l * DFF * DMODEL, b1 + l * DFF);
        ffn2_ks<<<dim3(NNODE / 64, 2), 128, KS_SMEM_BYTES>>>(
            w2t + (size_t)l * DMODEL * DFF, b2 + l * DMODEL);
    }

    readout_kernel<<<BGR / 4, 128>>>((const float4*)fc_w, fc_b, out);
}

// round 5
// speedup vs baseline: 1.7869x; 1.7869x over previous
#include <cuda_runtime.h>
#include <cuda_bf16.h>
#include <cstdint>
#include <math.h>

typedef unsigned int uint;
typedef unsigned long long ull;

// ---------------------------------------------------------------------------
// Problem constants
// ---------------------------------------------------------------------------
#define BGR   16384
#define NPG   9
#define NNODE (BGR * NPG)      // 147456
#define DM    128
#define DFF   512
#define NL    4
#define EPG   16

#define NTILES (NNODE / 128)   // 1152

// smem tile geometry: 128 rows x 128 bf16, padded row stride 136 elems (272 B)
#define LDT_B   272
#define TILE_B  (128 * LDT_B)          // 34816
#define A_HI    0
#define A_LO    TILE_B
#define B_HI    (2 * TILE_B)
#define B_LO    (3 * TILE_B)
#define STAGE_O (2 * TILE_B)           // f32 stage reuses B area (67584 <= 69632)
#define GM_SMEM (4 * TILE_B)           // 139264

// ---------------------------------------------------------------------------
// Scratch (device globals) — activations as packed split bf16:
// uint32 = (bf16 hi) | (bf16 lo << 16); value = hi + lo
// ---------------------------------------------------------------------------
__device__ uint  g_h  [(size_t)NNODE * DM];
__device__ uint  g_agg[(size_t)NNODE * DM];
__device__ uint  g_mid[(size_t)NNODE * DFF];
__device__ float g_inv[NNODE];
__device__ uint  g_WgT[(size_t)NL * DM * DM];    // [l][n][k]
__device__ uint  g_W1T[(size_t)NL * DFF * DM];   // [l][n(512)][k(128)]
__device__ uint  g_W2T[(size_t)NL * DM * DFF];   // [l][n(128)][k(512)]

// ---------------------------------------------------------------------------
// helpers
// ---------------------------------------------------------------------------
__device__ __forceinline__ uint smem_u32(const void* p) {
    uint a;
    asm("{ .reg .u64 t; cvta.to.shared.u64 t, %1; cvt.u32.u64 %0, t; }" : "=r"(a) : "l"(p));
    return a;
}

__device__ __forceinline__ void ldsm4(uint* r, uint addr) {
    asm volatile("ldmatrix.sync.aligned.m8n8.x4.shared.b16 {%0,%1,%2,%3}, [%4];"
        : "=r"(r[0]), "=r"(r[1]), "=r"(r[2]), "=r"(r[3]) : "r"(addr));
}

__device__ __forceinline__ void mma_bf16(float* c, const uint* a, const uint* b) {
    asm volatile("mma.sync.aligned.m16n8k16.row.col.f32.bf16.bf16.f32 "
        "{%0,%1,%2,%3}, {%4,%5,%6,%7}, {%8,%9}, {%0,%1,%2,%3};"
        : "+f"(c[0]), "+f"(c[1]), "+f"(c[2]), "+f"(c[3])
        : "r"(a[0]), "r"(a[1]), "r"(a[2]), "r"(a[3]), "r"(b[0]), "r"(b[1]));
}

__device__ __forceinline__ uint pksplit(float v) {
    __nv_bfloat16 h = __float2bfloat16(v);
    __nv_bfloat16 l = __float2bfloat16(v - __bfloat162float(h));
    return (uint)__bfloat16_as_ushort(h) | ((uint)__bfloat16_as_ushort(l) << 16);
}
__device__ __forceinline__ float unpks(uint u) {
    return __bfloat162float(__ushort_as_bfloat16((unsigned short)(u & 0xffffu)))
         + __bfloat162float(__ushort_as_bfloat16((unsigned short)(u >> 16)));
}

// ---------------------------------------------------------------------------
// Load a 128x128 packed tile -> separate hi/lo bf16 smem tiles (stride 272B)
// 256 threads.
// ---------------------------------------------------------------------------
__device__ __forceinline__ void load_split_tile(const uint* __restrict__ g, int ldg,
                                                char* bp, int offHi, int offLo, int tid) {
#pragma unroll
    for (int i = 0; i < 16; i++) {
        int idx = tid + 256 * i;       // 4096 uint4s
        int r = idx >> 5, q = idx & 31;
        uint4 u = *reinterpret_cast<const uint4*>(g + (size_t)r * ldg + 4 * q);
        uint2 hq = make_uint2((u.x & 0xffffu) | ((u.y & 0xffffu) << 16),
                              (u.z & 0xffffu) | ((u.w & 0xffffu) << 16));
        uint2 lq = make_uint2((u.x >> 16) | (u.y & 0xffff0000u),
                              (u.z >> 16) | (u.w & 0xffff0000u));
        int b = r * LDT_B + q * 8;
        *reinterpret_cast<uint2*>(bp + offHi + b) = hq;
        *reinterpret_cast<uint2*>(bp + offLo + b) = lq;
    }
}

// ---------------------------------------------------------------------------
// Core: warp tile 32(M) x 64(N), K=128 chunk, 3-pass split accumulate.
// offA/offB are lane-dependent byte offsets (precomputed).
// ---------------------------------------------------------------------------
__device__ __forceinline__ void mma_chunk(uint aHi, uint aLo, uint bHi, uint bLo,
                                          const uint* offA, const uint* offB,
                                          float acc[2][8][4]) {
#pragma unroll
    for (int ks = 0; ks < 8; ks++) {
        uint kb = ks * 32;             // 16 bf16 = 32 bytes
        uint ah[2][4], al[2][4], bh[4][4], bl[4][4];
        ldsm4(ah[0], aHi + offA[0] + kb);
        ldsm4(ah[1], aHi + offA[1] + kb);
        ldsm4(al[0], aLo + offA[0] + kb);
        ldsm4(al[1], aLo + offA[1] + kb);
#pragma unroll
        for (int p = 0; p < 4; p++) {
            ldsm4(bh[p], bHi + offB[p] + kb);
            ldsm4(bl[p], bLo + offB[p] + kb);
        }
#pragma unroll
        for (int im = 0; im < 2; im++)
#pragma unroll
            for (int p = 0; p < 4; p++) {
                mma_bf16(acc[im][2 * p],     ah[im], &bh[p][0]);
                mma_bf16(acc[im][2 * p + 1], ah[im], &bh[p][2]);
                mma_bf16(acc[im][2 * p],     ah[im], &bl[p][0]);
                mma_bf16(acc[im][2 * p + 1], ah[im], &bl[p][2]);
                mma_bf16(acc[im][2 * p],     al[im], &bh[p][0]);
                mma_bf16(acc[im][2 * p + 1], al[im], &bh[p][2]);
            }
    }
}

__device__ __forceinline__ void zero_acc(float acc[2][8][4]) {
#pragma unroll
    for (int im = 0; im < 2; im++)
#pragma unroll
        for (int in = 0; in < 8; in++)
#pragma unroll
            for (int r = 0; r < 4; r++) acc[im][in][r] = 0.f;
}

__device__ __forceinline__ void make_offs(int lane, int wm, int wn,
                                          uint* offA, uint* offB) {
#pragma unroll
    for (int im = 0; im < 2; im++)
        offA[im] = (uint)((wm * 32 + im * 16 + (lane & 15)) * LDT_B + ((lane >> 4) << 4));
#pragma unroll
    for (int p = 0; p < 4; p++)
        offB[p] = (uint)((wn * 64 + p * 16 + (lane & 7) + ((lane >> 4) << 3)) * LDT_B
                         + (((lane >> 3) & 1) << 4));
}

// stage acc (raw) into f32 smem [128][132]
__device__ __forceinline__ void stage_acc(float* st, int wm, int wn, int lane,
                                          float acc[2][8][4]) {
    int gid = lane >> 2, tig = lane & 3;
#pragma unroll
    for (int im = 0; im < 2; im++)
#pragma unroll
        for (int in = 0; in < 8; in++)
#pragma unroll
            for (int r = 0; r < 4; r++) {
                int row = wm * 32 + im * 16 + gid + 8 * (r >> 1);
                int col = wn * 64 + in * 8 + 2 * tig + (r & 1);
                st[row * 132 + col] = acc[im][in][r];
            }
}

// ---------------------------------------------------------------------------
// K0: degree -> inv_sqrt_deg
// ---------------------------------------------------------------------------
__global__ void deg_kernel(const int* __restrict__ dst) {
    int g = blockIdx.x * blockDim.x + threadIdx.x;
    if (g >= BGR) return;
    int base = g * NPG;
    int cnt[NPG];
#pragma unroll
    for (int j = 0; j < NPG; j++) cnt[j] = 1;
#pragma unroll
    for (int e = 0; e < EPG; e++) {
        int dl = dst[g * EPG + e] - base;
#pragma unroll
        for (int j = 0; j < NPG; j++) cnt[j] += (dl == j) ? 1 : 0;
    }
#pragma unroll
    for (int j = 0; j < NPG; j++)
        g_inv[base + j] = rsqrtf((float)cnt[j]);
}

// ---------------------------------------------------------------------------
// K1: embedding -> g_h packed split
// ---------------------------------------------------------------------------
__global__ void embed_kernel(const float4* __restrict__ opt,
                             const float4* __restrict__ de,
                             const int* __restrict__ op_idx) {
    int idx = blockIdx.x * blockDim.x + threadIdx.x;   // NNODE*32
    int n = idx >> 5, c = idx & 31;
    float4 t = opt[op_idx[n] * 32 + c];
    float4 d = de[c];
    uint4 o = make_uint4(pksplit(t.x + d.x), pksplit(t.y + d.y),
                         pksplit(t.z + d.z), pksplit(t.w + d.w));
    reinterpret_cast<uint4*>(g_h)[idx] = o;
}

// ---------------------------------------------------------------------------
// K2: per-graph aggregation (packed in / packed out, no atomics)
// ---------------------------------------------------------------------------
__global__ __launch_bounds__(128) void agg_kernel(const int* __restrict__ src,
                                                  const int* __restrict__ dst) {
    __shared__ float hs[NPG * DM];
    __shared__ float ag[NPG * DM];
    __shared__ float invs[NPG];
    __shared__ float we[EPG];
    __shared__ int sl[EPG], dl[EPG];

    int g = blockIdx.x, t = threadIdx.x;
    int nbase = g * NPG;
    if (t < NPG) invs[t] = g_inv[nbase + t];
    if (t < EPG) {
        sl[t] = src[g * EPG + t] - nbase;
        dl[t] = dst[g * EPG + t] - nbase;
    }
    __syncthreads();
    if (t < EPG) we[t] = invs[sl[t]] * invs[dl[t]];
#pragma unroll
    for (int j = 0; j < NPG; j++) {
        float v = unpks(g_h[(size_t)(nbase + j) * DM + t]);
        hs[j * DM + t] = v;
        ag[j * DM + t] = invs[j] * invs[j] * v;
    }
    __syncthreads();
#pragma unroll
    for (int e = 0; e < EPG; e++)
        ag[dl[e] * DM + t] += we[e] * hs[sl[e] * DM + t];
#pragma unroll
    for (int j = 0; j < NPG; j++)
        g_agg[(size_t)(nbase + j) * DM + t] = pksplit(ag[j * DM + t]);
}

// ---------------------------------------------------------------------------
// Weight prep: dst_packed[l][c][r] = split(src[l][r][c])
// ---------------------------------------------------------------------------
__global__ void prep_w(const float* __restrict__ src, uint* __restrict__ dst,
                       int R, int C) {
    int l = blockIdx.z;
    src += (size_t)l * R * C;
    dst += (size_t)l * R * C;
    int n = blockIdx.x * blockDim.x + threadIdx.x;
    if (n >= R * C) return;
    int c = n / R, r = n % R;
    dst[n] = pksplit(src[(size_t)r * C + c]);
}

// ---------------------------------------------------------------------------
// K3: GCN  g_h = LN(relu(agg @ Wg + bg))
// ---------------------------------------------------------------------------
__global__ __launch_bounds__(256) void gcn_mma(const uint* __restrict__ WgT,
                                               const float* __restrict__ bg,
                                               const float* __restrict__ lng,
                                               const float* __restrict__ lnb) {
    extern __shared__ char dsm[];
    __shared__ __align__(16) float sBias[DM], sLng[DM], sLnb[DM];

    int tid = threadIdx.x, lane = tid & 31, wid = tid >> 5;
    int wm = wid & 3, wn = wid >> 2;
    if (tid < DM) { sBias[tid] = bg[tid]; sLng[tid] = lng[tid]; sLnb[tid] = lnb[tid]; }

    uint sb = smem_u32(dsm);
    int m0 = blockIdx.x * 128;
    load_split_tile(g_agg + (size_t)m0 * DM, DM, dsm, A_HI, A_LO, tid);
    load_split_tile(WgT, DM, dsm, B_HI, B_LO, tid);

    uint offA[2], offB[4];
    make_offs(lane, wm, wn, offA, offB);
    float acc[2][8][4];
    zero_acc(acc);
    __syncthreads();
    mma_chunk(sb + A_HI, sb + A_LO, sb + B_HI, sb + B_LO, offA, offB, acc);
    __syncthreads();
    float* stage = (float*)(dsm + STAGE_O);
    stage_acc(stage, wm, wn, lane, acc);
    __syncthreads();

    // LayerNorm: warp per row, 16 rows/warp
    float4 gq = *reinterpret_cast<const float4*>(&sLng[lane * 4]);
    float4 bq = *reinterpret_cast<const float4*>(&sLnb[lane * 4]);
    float4 bb = *reinterpret_cast<const float4*>(&sBias[lane * 4]);
    for (int it = 0; it < 16; it++) {
        int r = wid * 16 + it;
        float4 x = *reinterpret_cast<const float4*>(&stage[r * 132 + lane * 4]);
        x.x = fmaxf(x.x + bb.x, 0.f); x.y = fmaxf(x.y + bb.y, 0.f);
        x.z = fmaxf(x.z + bb.z, 0.f); x.w = fmaxf(x.w + bb.w, 0.f);
        float s = x.x + x.y + x.z + x.w;
#pragma unroll
        for (int o = 16; o; o >>= 1) s += __shfl_xor_sync(0xffffffffu, s, o);
        float mu = s * (1.f / 128.f);
        float dx = x.x - mu, dy = x.y - mu, dz = x.z - mu, dw = x.w - mu;
        float q = dx * dx + dy * dy + dz * dz + dw * dw;
#pragma unroll
        for (int o = 16; o; o >>= 1) q += __shfl_xor_sync(0xffffffffu, q, o);
        float rs = rsqrtf(q * (1.f / 128.f) + 1e-5f);
        uint4 o4 = make_uint4(pksplit(dx * rs * gq.x + bq.x),
                              pksplit(dy * rs * gq.y + bq.y),
                              pksplit(dz * rs * gq.z + bq.z),
                              pksplit(dw * rs * gq.w + bq.w));
        *reinterpret_cast<uint4*>(g_h + (size_t)(m0 + r) * DM + lane * 4) = o4;
    }
}

// ---------------------------------------------------------------------------
// K4: FFN1  g_mid = relu(g_h @ W1 + b1)  — A resident, 4 N-chunks of 128
// ---------------------------------------------------------------------------
__global__ __launch_bounds__(256) void ffn1_mma(const uint* __restrict__ W1T,
                                                const float* __restrict__ b1) {
    extern __shared__ char dsm[];
    __shared__ __align__(16) float sB1[DFF];

    int tid = threadIdx.x, lane = tid & 31, wid = tid >> 5;
    int wm = wid & 3, wn = wid >> 2;
    for (int i = tid; i < DFF; i += 256) sB1[i] = b1[i];

    uint sb = smem_u32(dsm);
    int m0 = blockIdx.x * 128;
    load_split_tile(g_h + (size_t)m0 * DM, DM, dsm, A_HI, A_LO, tid);

    uint offA[2], offB[4];
    make_offs(lane, wm, wn, offA, offB);
    float* stage = (float*)(dsm + STAGE_O);

    for (int c = 0; c < 4; c++) {
        __syncthreads();
        load_split_tile(W1T + (size_t)c * 128 * DM, DM, dsm, B_HI, B_LO, tid);
        float acc[2][8][4];
        zero_acc(acc);
        __syncthreads();
        mma_chunk(sb + A_HI, sb + A_LO, sb + B_HI, sb + B_LO, offA, offB, acc);
        __syncthreads();
        stage_acc(stage, wm, wn, lane, acc);
        __syncthreads();
#pragma unroll
        for (int i = 0; i < 16; i++) {
            int idx = tid + 256 * i;
            int r = idx >> 5, q = idx & 31;
            float4 v = *reinterpret_cast<const float4*>(&stage[r * 132 + 4 * q]);
            int nb = c * 128 + 4 * q;
            uint4 o = make_uint4(pksplit(fmaxf(v.x + sB1[nb], 0.f)),
                                 pksplit(fmaxf(v.y + sB1[nb + 1], 0.f)),
                                 pksplit(fmaxf(v.z + sB1[nb + 2], 0.f)),
                                 pksplit(fmaxf(v.w + sB1[nb + 3], 0.f)));
            *reinterpret_cast<uint4*>(g_mid + (size_t)(m0 + r) * DFF + nb) = o;
        }
    }
}

// ---------------------------------------------------------------------------
// K5: FFN2  g_h = g_h + g_mid @ W2 + b2  — 4 K-chunks, reg accumulate
// ---------------------------------------------------------------------------
__global__ __launch_bounds__(256) void ffn2_mma(const uint* __restrict__ W2T,
                                                const float* __restrict__ b2) {
    extern __shared__ char dsm[];
    __shared__ __align__(16) float sB2[DM];

    int tid = threadIdx.x, lane = tid & 31, wid = tid >> 5;
    int wm = wid & 3, wn = wid >> 2;
    if (tid < DM) sB2[tid] = b2[tid];

    uint sb = smem_u32(dsm);
    int m0 = blockIdx.x * 128;
    uint offA[2], offB[4];
    make_offs(lane, wm, wn, offA, offB);
    float acc[2][8][4];
    zero_acc(acc);

    for (int kc = 0; kc < 4; kc++) {
        __syncthreads();
        load_split_tile(g_mid + (size_t)m0 * DFF + kc * 128, DFF, dsm, A_HI, A_LO, tid);
        load_split_tile(W2T + kc * 128, DFF, dsm, B_HI, B_LO, tid);
        __syncthreads();
        mma_chunk(sb + A_HI, sb + A_LO, sb + B_HI, sb + B_LO, offA, offB, acc);
    }
    __syncthreads();
    float* stage = (float*)(dsm + STAGE_O);
    stage_acc(stage, wm, wn, lane, acc);
    __syncthreads();
#pragma unroll
    for (int i = 0; i < 16; i++) {
        int idx = tid + 256 * i;
        int r = idx >> 5, q = idx & 31;
        float4 v = *reinterpret_cast<const float4*>(&stage[r * 132 + 4 * q]);
        uint* hp = g_h + (size_t)(m0 + r) * DM + 4 * q;
        uint4 hold = *reinterpret_cast<const uint4*>(hp);
        uint4 o = make_uint4(pksplit(v.x + sB2[4 * q]     + unpks(hold.x)),
                             pksplit(v.y + sB2[4 * q + 1] + unpks(hold.y)),
                             pksplit(v.z + sB2[4 * q + 2] + unpks(hold.z)),
                             pksplit(v.w + sB2[4 * q + 3] + unpks(hold.w)));
        *reinterpret_cast<uint4*>(hp) = o;
    }
}

// ---------------------------------------------------------------------------
// K6: readout
// ---------------------------------------------------------------------------
__global__ __launch_bounds__(128) void readout_kernel(const float4* __restrict__ fcw,
                                                      const float* __restrict__ fcb,
                                                      float* __restrict__ out) {
    int w = threadIdx.x >> 5, lane = threadIdx.x & 31;
    int g = blockIdx.x * 4 + w;
    const uint4* h4 = reinterpret_cast<const uint4*>(g_h);
    size_t base = (size_t)g * NPG * 32;
    float4 s = make_float4(0.f, 0.f, 0.f, 0.f);
#pragma unroll
    for (int j = 0; j < NPG; j++) {
        uint4 v = h4[base + j * 32 + lane];
        s.x += unpks(v.x); s.y += unpks(v.y); s.z += unpks(v.z); s.w += unpks(v.w);
    }
    float4 wv = fcw[lane];
    float p = s.x * wv.x + s.y * wv.y + s.z * wv.z + s.w * wv.w;
#pragma unroll
    for (int o = 16; o; o >>= 1) p += __shfl_xor_sync(0xffffffffu, p, o);
    if (lane == 0)
        out[g] = 1.f / (1.f + expf(-(p * (1.f / 9.f) + fcb[0])));
}

// ---------------------------------------------------------------------------
// Launcher
// ---------------------------------------------------------------------------
extern "C" void kernel_launch(void* const* d_in, const int* in_sizes, int n_in,
                              void* d_out, int out_size) {
    const float* op_table   = (const float*)d_in[0];
    const float* device_emb = (const float*)d_in[1];
    const float* Wg         = (const float*)d_in[2];
    const float* bg         = (const float*)d_in[3];
    const float* ln_g       = (const float*)d_in[4];
    const float* ln_b       = (const float*)d_in[5];
    const float* W1         = (const float*)d_in[6];
    const float* b1         = (const float*)d_in[7];
    const float* W2         = (const float*)d_in[8];
    const float* b2         = (const float*)d_in[9];
    const float* fc_w       = (const float*)d_in[10];
    const float* fc_b       = (const float*)d_in[11];
    const int*   op_idx     = (const int*)d_in[12];
    const int*   src        = (const int*)d_in[13];
    const int*   dst        = (const int*)d_in[14];
    float* out = (float*)d_out;

    cudaFuncSetAttribute(gcn_mma,  cudaFuncAttributeMaxDynamicSharedMemorySize, GM_SMEM);
    cudaFuncSetAttribute(ffn1_mma, cudaFuncAttributeMaxDynamicSharedMemorySize, GM_SMEM);
    cudaFuncSetAttribute(ffn2_mma, cudaFuncAttributeMaxDynamicSharedMemorySize, GM_SMEM);

    uint *wgt, *w1t, *w2t;
    cudaGetSymbolAddress((void**)&wgt, g_WgT);
    cudaGetSymbolAddress((void**)&w1t, g_W1T);
    cudaGetSymbolAddress((void**)&w2t, g_W2T);

    prep_w<<<dim3((DM * DM + 255) / 256, 1, NL), 256>>>(Wg, wgt, DM, DM);
    prep_w<<<dim3((DM * DFF + 255) / 256, 1, NL), 256>>>(W1, w1t, DM, DFF);
    prep_w<<<dim3((DM * DFF + 255) / 256, 1, NL), 256>>>(W2, w2t, DFF, DM);

    deg_kernel<<<BGR / 256, 256>>>(dst);
    embed_kernel<<<(NNODE * 32) / 256, 256>>>(
        (const float4*)op_table, (const float4*)device_emb, op_idx);

    for (int l = 0; l < NL; l++) {
        agg_kernel<<<BGR, 128>>>(src, dst);
        gcn_mma<<<NTILES, 256, GM_SMEM>>>(
            wgt + (size_t)l * DM * DM, bg + l * DM, ln_g + l * DM, ln_b + l * DM);
        ffn1_mma<<<NTILES, 256, GM_SMEM>>>(
            w1t + (size_t)l * DFF * DM, b1 + l * DFF);
        ffn2_mma<<<NTILES, 256, GM_SMEM>>>(
            w2t + (size_t)l * DM * DFF, b2 + l * DM);
    }

    readout_kernel<<<BGR / 4, 128>>>((const float4*)fc_w, fc_b, out);
}

// round 6
// speedup vs baseline: 2.3949x; 1.3403x over previous
#include <cuda_runtime.h>
#include <cuda_bf16.h>
#include <cstdint>
#include <math.h>

typedef unsigned int uint;
typedef unsigned long long ull;
typedef unsigned short ushort;

// ---------------------------------------------------------------------------
// Problem constants
// ---------------------------------------------------------------------------
#define BGR   16384
#define NPG   9
#define NNODE (BGR * NPG)      // 147456
#define DM    128
#define DFF   512
#define NL    4
#define EPG   16

#define NTILES (NNODE / 128)   // 1152

// smem tile geometry: 128 rows x 128 bf16, padded row stride 136 elems (272 B)
#define LDT_B   272
#define TILE_B  (128 * LDT_B)          // 34816

// gcn kernel layout
#define A_HI    0
#define A_LO    TILE_B
#define B_HI    (2 * TILE_B)
#define B_LO    (3 * TILE_B)
#define STAGE_O (2 * TILE_B)
#define GM_SMEM (4 * TILE_B)           // 139264

// fused ffn kernel layout
#define H_HI    0
#define H_LO    TILE_B
#define W_HI    (2 * TILE_B)
#define W_LO    (3 * TILE_B)
#define M_HI    (4 * TILE_B)
#define M_LO    (5 * TILE_B)
#define FF_SMEM (6 * TILE_B)           // 208896

// ---------------------------------------------------------------------------
// Scratch (device globals) — activations as packed split bf16:
// uint32 = (bf16 hi) | (bf16 lo << 16); value = hi + lo
// ---------------------------------------------------------------------------
__device__ uint  g_h  [(size_t)NNODE * DM];
__device__ uint  g_agg[(size_t)NNODE * DM];
__device__ float g_inv[NNODE];
__device__ uint  g_WgT[(size_t)NL * DM * DM];    // [l][n][k]
__device__ uint  g_W1T[(size_t)NL * DFF * DM];   // [l][n(512)][k(128)]
__device__ uint  g_W2T[(size_t)NL * DM * DFF];   // [l][n(128)][k(512)]

// ---------------------------------------------------------------------------
// helpers
// ---------------------------------------------------------------------------
__device__ __forceinline__ uint smem_u32(const void* p) {
    uint a;
    asm("{ .reg .u64 t; cvta.to.shared.u64 t, %1; cvt.u32.u64 %0, t; }" : "=r"(a) : "l"(p));
    return a;
}

__device__ __forceinline__ void ldsm4(uint* r, uint addr) {
    asm volatile("ldmatrix.sync.aligned.m8n8.x4.shared.b16 {%0,%1,%2,%3}, [%4];"
        : "=r"(r[0]), "=r"(r[1]), "=r"(r[2]), "=r"(r[3]) : "r"(addr));
}

__device__ __forceinline__ void mma_bf16(float* c, const uint* a, const uint* b) {
    asm volatile("mma.sync.aligned.m16n8k16.row.col.f32.bf16.bf16.f32 "
        "{%0,%1,%2,%3}, {%4,%5,%6,%7}, {%8,%9}, {%0,%1,%2,%3};"
        : "+f"(c[0]), "+f"(c[1]), "+f"(c[2]), "+f"(c[3])
        : "r"(a[0]), "r"(a[1]), "r"(a[2]), "r"(a[3]), "r"(b[0]), "r"(b[1]));
}

__device__ __forceinline__ uint pksplit(float v) {
    __nv_bfloat16 h = __float2bfloat16(v);
    __nv_bfloat16 l = __float2bfloat16(v - __bfloat162float(h));
    return (uint)__bfloat16_as_ushort(h) | ((uint)__bfloat16_as_ushort(l) << 16);
}
__device__ __forceinline__ float unpks(uint u) {
    return __bfloat162float(__ushort_as_bfloat16((ushort)(u & 0xffffu)))
         + __bfloat162float(__ushort_as_bfloat16((ushort)(u >> 16)));
}
__device__ __forceinline__ float bfu(uint s) {
    return __bfloat162float(__ushort_as_bfloat16((ushort)s));
}

// ---------------------------------------------------------------------------
// Load a 128x128 packed tile -> separate hi/lo bf16 smem tiles (stride 272B)
// 256 threads.
// ---------------------------------------------------------------------------
__device__ __forceinline__ void load_split_tile(const uint* __restrict__ g, int ldg,
                                                char* bp, int offHi, int offLo, int tid) {
#pragma unroll
    for (int i = 0; i < 16; i++) {
        int idx = tid + 256 * i;       // 4096 uint4s
        int r = idx >> 5, q = idx & 31;
        uint4 u = *reinterpret_cast<const uint4*>(g + (size_t)r * ldg + 4 * q);
        uint2 hq = make_uint2((u.x & 0xffffu) | ((u.y & 0xffffu) << 16),
                              (u.z & 0xffffu) | ((u.w & 0xffffu) << 16));
        uint2 lq = make_uint2((u.x >> 16) | (u.y & 0xffff0000u),
                              (u.z >> 16) | (u.w & 0xffff0000u));
        int b = r * LDT_B + q * 8;
        *reinterpret_cast<uint2*>(bp + offHi + b) = hq;
        *reinterpret_cast<uint2*>(bp + offLo + b) = lq;
    }
}

// ---------------------------------------------------------------------------
// Core: warp tile 32(M) x 64(N), K=128 chunk, 3-pass split accumulate.
// ---------------------------------------------------------------------------
__device__ __forceinline__ void mma_chunk(uint aHi, uint aLo, uint bHi, uint bLo,
                                          const uint* offA, const uint* offB,
                                          float acc[2][8][4]) {
#pragma unroll
    for (int ks = 0; ks < 8; ks++) {
        uint kb = ks * 32;             // 16 bf16 = 32 bytes
        uint ah[2][4], al[2][4], bh[4][4], bl[4][4];
        ldsm4(ah[0], aHi + offA[0] + kb);
        ldsm4(ah[1], aHi + offA[1] + kb);
        ldsm4(al[0], aLo + offA[0] + kb);
        ldsm4(al[1], aLo + offA[1] + kb);
#pragma unroll
        for (int p = 0; p < 4; p++) {
            ldsm4(bh[p], bHi + offB[p] + kb);
            ldsm4(bl[p], bLo + offB[p] + kb);
        }
#pragma unroll
        for (int im = 0; im < 2; im++)
#pragma unroll
            for (int p = 0; p < 4; p++) {
                mma_bf16(acc[im][2 * p],     ah[im], &bh[p][0]);
                mma_bf16(acc[im][2 * p + 1], ah[im], &bh[p][2]);
                mma_bf16(acc[im][2 * p],     ah[im], &bl[p][0]);
                mma_bf16(acc[im][2 * p + 1], ah[im], &bl[p][2]);
                mma_bf16(acc[im][2 * p],     al[im], &bh[p][0]);
                mma_bf16(acc[im][2 * p + 1], al[im], &bh[p][2]);
            }
    }
}

__device__ __forceinline__ void zero_acc(float acc[2][8][4]) {
#pragma unroll
    for (int im = 0; im < 2; im++)
#pragma unroll
        for (int in = 0; in < 8; in++)
#pragma unroll
            for (int r = 0; r < 4; r++) acc[im][in][r] = 0.f;
}

__device__ __forceinline__ void make_offs(int lane, int wm, int wn,
                                          uint* offA, uint* offB) {
#pragma unroll
    for (int im = 0; im < 2; im++)
        offA[im] = (uint)((wm * 32 + im * 16 + (lane & 15)) * LDT_B + ((lane >> 4) << 4));
#pragma unroll
    for (int p = 0; p < 4; p++)
        offB[p] = (uint)((wn * 64 + p * 16 + (lane & 7) + ((lane >> 4) << 3)) * LDT_B
                         + (((lane >> 3) & 1) << 4));
}

// stage acc (raw) into f32 smem [128][132]
__device__ __forceinline__ void stage_acc(float* st, int wm, int wn, int lane,
                                          float acc[2][8][4]) {
    int gid = lane >> 2, tig = lane & 3;
#pragma unroll
    for (int im = 0; im < 2; im++)
#pragma unroll
        for (int in = 0; in < 8; in++)
#pragma unroll
            for (int r = 0; r < 4; r++) {
                int row = wm * 32 + im * 16 + gid + 8 * (r >> 1);
                int col = wn * 64 + in * 8 + 2 * tig + (r & 1);
                st[row * 132 + col] = acc[im][in][r];
            }
}

// ---------------------------------------------------------------------------
// K0: degree -> inv_sqrt_deg
// ---------------------------------------------------------------------------
__global__ void deg_kernel(const int* __restrict__ dst) {
    int g = blockIdx.x * blockDim.x + threadIdx.x;
    if (g >= BGR) return;
    int base = g * NPG;
    int cnt[NPG];
#pragma unroll
    for (int j = 0; j < NPG; j++) cnt[j] = 1;
#pragma unroll
    for (int e = 0; e < EPG; e++) {
        int dl = dst[g * EPG + e] - base;
#pragma unroll
        for (int j = 0; j < NPG; j++) cnt[j] += (dl == j) ? 1 : 0;
    }
#pragma unroll
    for (int j = 0; j < NPG; j++)
        g_inv[base + j] = rsqrtf((float)cnt[j]);
}

// ---------------------------------------------------------------------------
// K1: embedding -> g_h packed split
// ---------------------------------------------------------------------------
__global__ void embed_kernel(const float4* __restrict__ opt,
                             const float4* __restrict__ de,
                             const int* __restrict__ op_idx) {
    int idx = blockIdx.x * blockDim.x + threadIdx.x;   // NNODE*32
    int n = idx >> 5, c = idx & 31;
    float4 t = opt[op_idx[n] * 32 + c];
    float4 d = de[c];
    uint4 o = make_uint4(pksplit(t.x + d.x), pksplit(t.y + d.y),
                         pksplit(t.z + d.z), pksplit(t.w + d.w));
    reinterpret_cast<uint4*>(g_h)[idx] = o;
}

// ---------------------------------------------------------------------------
// K2: per-graph aggregation (packed in / packed out, no atomics)
// ---------------------------------------------------------------------------
__global__ __launch_bounds__(128) void agg_kernel(const int* __restrict__ src,
                                                  const int* __restrict__ dst) {
    __shared__ float hs[NPG * DM];
    __shared__ float ag[NPG * DM];
    __shared__ float invs[NPG];
    __shared__ float we[EPG];
    __shared__ int sl[EPG], dl[EPG];

    int g = blockIdx.x, t = threadIdx.x;
    int nbase = g * NPG;
    if (t < NPG) invs[t] = g_inv[nbase + t];
    if (t < EPG) {
        sl[t] = src[g * EPG + t] - nbase;
        dl[t] = dst[g * EPG + t] - nbase;
    }
    __syncthreads();
    if (t < EPG) we[t] = invs[sl[t]] * invs[dl[t]];
#pragma unroll
    for (int j = 0; j < NPG; j++) {
        float v = unpks(g_h[(size_t)(nbase + j) * DM + t]);
        hs[j * DM + t] = v;
        ag[j * DM + t] = invs[j] * invs[j] * v;
    }
    __syncthreads();
#pragma unroll
    for (int e = 0; e < EPG; e++)
        ag[dl[e] * DM + t] += we[e] * hs[sl[e] * DM + t];
#pragma unroll
    for (int j = 0; j < NPG; j++)
        g_agg[(size_t)(nbase + j) * DM + t] = pksplit(ag[j * DM + t]);
}

// ---------------------------------------------------------------------------
// Weight prep: dst_packed[l][c][r] = split(src[l][r][c])
// ---------------------------------------------------------------------------
__global__ void prep_w(const float* __restrict__ src, uint* __restrict__ dst,
                       int R, int C) {
    int l = blockIdx.z;
    src += (size_t)l * R * C;
    dst += (size_t)l * R * C;
    int n = blockIdx.x * blockDim.x + threadIdx.x;
    if (n >= R * C) return;
    int c = n / R, r = n % R;
    dst[n] = pksplit(src[(size_t)r * C + c]);
}

// ---------------------------------------------------------------------------
// K3: GCN  g_h = LN(relu(agg @ Wg + bg))
// ---------------------------------------------------------------------------
__global__ __launch_bounds__(256) void gcn_mma(const uint* __restrict__ WgT,
                                               const float* __restrict__ bg,
                                               const float* __restrict__ lng,
                                               const float* __restrict__ lnb) {
    extern __shared__ char dsm[];
    __shared__ __align__(16) float sBias[DM], sLng[DM], sLnb[DM];

    int tid = threadIdx.x, lane = tid & 31, wid = tid >> 5;
    int wm = wid & 3, wn = wid >> 2;
    if (tid < DM) { sBias[tid] = bg[tid]; sLng[tid] = lng[tid]; sLnb[tid] = lnb[tid]; }

    uint sb = smem_u32(dsm);
    int m0 = blockIdx.x * 128;
    load_split_tile(g_agg + (size_t)m0 * DM, DM, dsm, A_HI, A_LO, tid);
    load_split_tile(WgT, DM, dsm, B_HI, B_LO, tid);

    uint offA[2], offB[4];
    make_offs(lane, wm, wn, offA, offB);
    float acc[2][8][4];
    zero_acc(acc);
    __syncthreads();
    mma_chunk(sb + A_HI, sb + A_LO, sb + B_HI, sb + B_LO, offA, offB, acc);
    __syncthreads();
    float* stage = (float*)(dsm + STAGE_O);
    stage_acc(stage, wm, wn, lane, acc);
    __syncthreads();

    // LayerNorm: warp per row, 16 rows/warp
    float4 gq = *reinterpret_cast<const float4*>(&sLng[lane * 4]);
    float4 bq = *reinterpret_cast<const float4*>(&sLnb[lane * 4]);
    float4 bb = *reinterpret_cast<const float4*>(&sBias[lane * 4]);
    for (int it = 0; it < 16; it++) {
        int r = wid * 16 + it;
        float4 x = *reinterpret_cast<const float4*>(&stage[r * 132 + lane * 4]);
        x.x = fmaxf(x.x + bb.x, 0.f); x.y = fmaxf(x.y + bb.y, 0.f);
        x.z = fmaxf(x.z + bb.z, 0.f); x.w = fmaxf(x.w + bb.w, 0.f);
        float s = x.x + x.y + x.z + x.w;
#pragma unroll
        for (int o = 16; o; o >>= 1) s += __shfl_xor_sync(0xffffffffu, s, o);
        float mu = s * (1.f / 128.f);
        float dx = x.x - mu, dy = x.y - mu, dz = x.z - mu, dw = x.w - mu;
        float q = dx * dx + dy * dy + dz * dz + dw * dw;
#pragma unroll
        for (int o = 16; o; o >>= 1) q += __shfl_xor_sync(0xffffffffu, q, o);
        float rs = rsqrtf(q * (1.f / 128.f) + 1e-5f);
        uint4 o4 = make_uint4(pksplit(dx * rs * gq.x + bq.x),
                              pksplit(dy * rs * gq.y + bq.y),
                              pksplit(dz * rs * gq.z + bq.z),
                              pksplit(dw * rs * gq.w + bq.w));
        *reinterpret_cast<uint4*>(g_h + (size_t)(m0 + r) * DM + lane * 4) = o4;
    }
}

// ---------------------------------------------------------------------------
// K4: fused FFN  g_h = h + relu(h @ W1 + b1) @ W2 + b2
// h tile resident in smem; mid chunks live only in smem. No g_mid.
// ---------------------------------------------------------------------------
__global__ __launch_bounds__(256) void ffn_fused(const uint* __restrict__ W1T,
                                                 const uint* __restrict__ W2T,
                                                 const float* __restrict__ b1,
                                                 const float* __restrict__ b2) {
    extern __shared__ char dsm[];
    __shared__ __align__(16) float sB1[DFF], sB2[DM];

    int tid = threadIdx.x, lane = tid & 31, wid = tid >> 5;
    int wm = wid & 3, wn = wid >> 2;
    int gid = lane >> 2, tig = lane & 3;
    for (int i = tid; i < DFF; i += 256) sB1[i] = b1[i];
    if (tid < DM) sB2[tid] = b2[tid];

    uint sb = smem_u32(dsm);
    int m0 = blockIdx.x * 128;
    load_split_tile(g_h + (size_t)m0 * DM, DM, dsm, H_HI, H_LO, tid);

    uint offA[2], offB[4];
    make_offs(lane, wm, wn, offA, offB);
    float acc2[2][8][4];
    zero_acc(acc2);

    for (int c = 0; c < 4; c++) {
        __syncthreads();                       // Wbuf free (prior mma2 done)
        load_split_tile(W1T + (size_t)c * 128 * DM, DM, dsm, W_HI, W_LO, tid);
        float acc1[2][8][4];
        zero_acc(acc1);
        __syncthreads();                       // H + W1c ready
        mma_chunk(sb + H_HI, sb + H_LO, sb + W_HI, sb + W_LO, offA, offB, acc1);

        // relu + bias, write split fragments directly into Mid buffer
#pragma unroll
        for (int im = 0; im < 2; im++)
#pragma unroll
            for (int in = 0; in < 8; in++)
#pragma unroll
                for (int r = 0; r < 4; r++) {
                    int row = wm * 32 + im * 16 + gid + 8 * (r >> 1);
                    int col = wn * 64 + in * 8 + 2 * tig + (r & 1);
                    float v = fmaxf(acc1[im][in][r] + sB1[c * 128 + col], 0.f);
                    uint u = pksplit(v);
                    *reinterpret_cast<ushort*>(dsm + M_HI + row * LDT_B + col * 2) =
                        (ushort)(u & 0xffffu);
                    *reinterpret_cast<ushort*>(dsm + M_LO + row * LDT_B + col * 2) =
                        (ushort)(u >> 16);
                }
        __syncthreads();                       // Mid ready; Wbuf free
        // W2 chunk c: W2T[n][k], k in [c*128, c*128+128)
        load_split_tile(W2T + c * 128, DFF, dsm, W_HI, W_LO, tid);
        __syncthreads();                       // Mid + W2c ready
        mma_chunk(sb + M_HI, sb + M_LO, sb + W_HI, sb + W_LO, offA, offB, acc2);
    }
    __syncthreads();
    float* stage = (float*)(dsm + W_HI);       // 67584 B <= 2*TILE_B
    stage_acc(stage, wm, wn, lane, acc2);
    __syncthreads();

    // epilogue: + b2 + residual (from resident H tile), coalesced packed store
#pragma unroll
    for (int i = 0; i < 16; i++) {
        int idx = tid + 256 * i;
        int r = idx >> 5, q = idx & 31;
        float4 v = *reinterpret_cast<const float4*>(&stage[r * 132 + 4 * q]);
        uint2 hh = *reinterpret_cast<const uint2*>(dsm + H_HI + r * LDT_B + 8 * q);
        uint2 hl = *reinterpret_cast<const uint2*>(dsm + H_LO + r * LDT_B + 8 * q);
        float h0 = bfu(hh.x & 0xffffu) + bfu(hl.x & 0xffffu);
        float h1 = bfu(hh.x >> 16)     + bfu(hl.x >> 16);
        float h2 = bfu(hh.y & 0xffffu) + bfu(hl.y & 0xffffu);
        float h3 = bfu(hh.y >> 16)     + bfu(hl.y >> 16);
        uint4 o = make_uint4(pksplit(v.x + sB2[4 * q]     + h0),
                             pksplit(v.y + sB2[4 * q + 1] + h1),
                             pksplit(v.z + sB2[4 * q + 2] + h2),
                             pksplit(v.w + sB2[4 * q + 3] + h3));
        *reinterpret_cast<uint4*>(g_h + (size_t)(m0 + r) * DM + 4 * q) = o;
    }
}

// ---------------------------------------------------------------------------
// K6: readout
// ---------------------------------------------------------------------------
__global__ __launch_bounds__(128) void readout_kernel(const float4* __restrict__ fcw,
                                                      const float* __restrict__ fcb,
                                                      float* __restrict__ out) {
    int w = threadIdx.x >> 5, lane = threadIdx.x & 31;
    int g = blockIdx.x * 4 + w;
    const uint4* h4 = reinterpret_cast<const uint4*>(g_h);
    size_t base = (size_t)g * NPG * 32;
    float4 s = make_float4(0.f, 0.f, 0.f, 0.f);
#pragma unroll
    for (int j = 0; j < NPG; j++) {
        uint4 v = h4[base + j * 32 + lane];
        s.x += unpks(v.x); s.y += unpks(v.y); s.z += unpks(v.z); s.w += unpks(v.w);
    }
    float4 wv = fcw[lane];
    float p = s.x * wv.x + s.y * wv.y + s.z * wv.z + s.w * wv.w;
#pragma unroll
    for (int o = 16; o; o >>= 1) p += __shfl_xor_sync(0xffffffffu, p, o);
    if (lane == 0)
        out[g] = 1.f / (1.f + expf(-(p * (1.f / 9.f) + fcb[0])));
}

// ---------------------------------------------------------------------------
// Launcher
// ---------------------------------------------------------------------------
extern "C" void kernel_launch(void* const* d_in, const int* in_sizes, int n_in,
                              void* d_out, int out_size) {
    const float* op_table   = (const float*)d_in[0];
    const float* device_emb = (const float*)d_in[1];
    const float* Wg         = (const float*)d_in[2];
    const float* bg         = (const float*)d_in[3];
    const float* ln_g       = (const float*)d_in[4];
    const float* ln_b       = (const float*)d_in[5];
    const float* W1         = (const float*)d_in[6];
    const float* b1         = (const float*)d_in[7];
    const float* W2         = (const float*)d_in[8];
    const float* b2         = (const float*)d_in[9];
    const float* fc_w       = (const float*)d_in[10];
    const float* fc_b       = (const float*)d_in[11];
    const int*   op_idx     = (const int*)d_in[12];
    const int*   src        = (const int*)d_in[13];
    const int*   dst        = (const int*)d_in[14];
    float* out = (float*)d_out;

    cudaFuncSetAttribute(gcn_mma,   cudaFuncAttributeMaxDynamicSharedMemorySize, GM_SMEM);
    cudaFuncSetAttribute(ffn_fused, cudaFuncAttributeMaxDynamicSharedMemorySize, FF_SMEM);

    uint *wgt, *w1t, *w2t;
    cudaGetSymbolAddress((void**)&wgt, g_WgT);
    cudaGetSymbolAddress((void**)&w1t, g_W1T);
    cudaGetSymbolAddress((void**)&w2t, g_W2T);

    prep_w<<<dim3((DM * DM + 255) / 256, 1, NL), 256>>>(Wg, wgt, DM, DM);
    prep_w<<<dim3((DM * DFF + 255) / 256, 1, NL), 256>>>(W1, w1t, DM, DFF);
    prep_w<<<dim3((DM * DFF + 255) / 256, 1, NL), 256>>>(W2, w2t, DFF, DM);

    deg_kernel<<<BGR / 256, 256>>>(dst);
    embed_kernel<<<(NNODE * 32) / 256, 256>>>(
        (const float4*)op_table, (const float4*)device_emb, op_idx);

    for (int l = 0; l < NL; l++) {
        agg_kernel<<<BGR, 128>>>(src, dst);
        gcn_mma<<<NTILES, 256, GM_SMEM>>>(
            wgt + (size_t)l * DM * DM, bg + l * DM, ln_g + l * DM, ln_b + l * DM);
        ffn_fused<<<NTILES, 256, FF_SMEM>>>(
            w1t + (size_t)l * DFF * DM, w2t + (size_t)l * DM * DFF,
            b1 + l * DFF, b2 + l * DM);
    }

    readout_kernel<<<BGR / 4, 128>>>((const float4*)fc_w, fc_b, out);
}